// round 15
// baseline (speedup 1.0000x reference)
#include <cuda_runtime.h>
#include <cuda_fp16.h>
#include <cstdint>

#define BATCH 2
#define SEQ   2048
#define HID   1024
#define NHEAD 16
#define HDIM  64
#define MROWS (BATCH*SEQ)   // 4096
#define BH    (BATCH*NHEAD) // 32

// ---------------- device scratch (allocation-free rule) ----------------
__device__ __half g_hsf[MROWS*HID];                     // hidden states plain fp16
__device__ __half g_wf[4*HID*HID];                      // Wq,Wk,Wv,Wo plain fp16
__device__ __half g_qf[BH*SEQ*HDIM];                    // Q plain [bh][s][d]
__device__ __half g_kf[BH*SEQ*HDIM];                    // K plain [bh][s][d]
__device__ __half g_vf[BH*SEQ*HDIM];                    // V plain [bh][s][d]
__device__ __half g_vtf[BH*HDIM*SEQ];                   // V^T plain [bh][d][s]
__device__ __half g_cxf[MROWS*HID];                     // ctx plain [m][n]

// ---------------- helpers ----------------
__device__ __forceinline__ unsigned pack2h(__half a, __half b) {
    __half2 t(a, b);
    return *reinterpret_cast<unsigned*>(&t);
}
__device__ __forceinline__ void mma_h(float* c, const unsigned* a,
                                      unsigned b0, unsigned b1) {
    asm volatile(
        "mma.sync.aligned.m16n8k16.row.col.f32.f16.f16.f32 "
        "{%0,%1,%2,%3},{%4,%5,%6,%7},{%8,%9},{%0,%1,%2,%3};\n"
        : "+f"(c[0]), "+f"(c[1]), "+f"(c[2]), "+f"(c[3])
        : "r"(a[0]), "r"(a[1]), "r"(a[2]), "r"(a[3]), "r"(b0), "r"(b1));
}
__device__ __forceinline__ float ex2(float x) {
    float r;
    asm("ex2.approx.f32 %0, %1;" : "=f"(r) : "f"(x));
    return r;
}
__device__ __forceinline__ uint32_t s2u(const void* p) {
    uint32_t a;
    asm("{ .reg .u64 t; cvta.to.shared.u64 t, %1; cvt.u32.u64 %0, t; }" : "=r"(a) : "l"(p));
    return a;
}
__device__ __forceinline__ void cp16(uint32_t saddr, const void* gaddr) {
    asm volatile("cp.async.cg.shared.global [%0], [%1], 16;" :: "r"(saddr), "l"(gaddr));
}
#define CP_COMMIT() asm volatile("cp.async.commit_group;" ::: "memory")
#define CP_WAIT1()  asm volatile("cp.async.wait_group 1;" ::: "memory")

#define GSTAGE 5120    // gemm stage: A(128x20)+W(128x20) u32 = 20 KB
#define ASTAGE 4608    // attn stage: K(64x36)+Vt(64x36) u32 = 18.4 KB
#define LOG2E  1.44269504f
#define SC2    0.18033688f   // 0.125 * log2(e)

// ---------------- fp32 -> fp16 plain convert (single tensor) ----------------
__global__ void conv16(const float4* __restrict__ in, uint2* __restrict__ outp, int n4)
{
    int i = blockIdx.x * 256 + threadIdx.x;
    if (i >= n4) return;
    float4 v = in[i];
    uint2 o;
    o.x = pack2h(__float2half_rn(v.x), __float2half_rn(v.y));
    o.y = pack2h(__float2half_rn(v.z), __float2half_rn(v.w));
    outp[i] = o;
}

// ---------------- fp32 -> fp16 convert, 4 weight matrices in one launch ----------------
__global__ void conv16x4(const float4* __restrict__ w0, const float4* __restrict__ w1,
                         const float4* __restrict__ w2, const float4* __restrict__ w3,
                         uint2* __restrict__ outp, int n4)
{
    int i = blockIdx.x * 256 + threadIdx.x;
    if (i >= n4) return;
    const float4* src = (blockIdx.y == 0) ? w0 : (blockIdx.y == 1) ? w1
                      : (blockIdx.y == 2) ? w2 : w3;
    float4 v = src[i];
    uint2 o;
    o.x = pack2h(__float2half_rn(v.x), __float2half_rn(v.y));
    o.y = pack2h(__float2half_rn(v.z), __float2half_rn(v.w));
    outp[(size_t)blockIdx.y * n4 + i] = o;
}

// ---------------- fused QKV GEMM (3-stage, R12-proven) ----------------
__global__ __launch_bounds__(256, 2) void gemmQKV(
    const __half* __restrict__ Af,
    const float* __restrict__ bq, const float* __restrict__ bk, const float* __restrict__ bv)
{
    extern __shared__ unsigned sm[];

    const int tid  = threadIdx.x;
    const int lane = tid & 31, warp = tid >> 5;
    const int wm = warp >> 1, wn = warp & 1;
    const int r = lane >> 2, c = lane & 3;
    const int m0 = blockIdx.y * 128;
    const int ng = blockIdx.x * 128;
    const int w  = ng >> 10;
    const int n0 = ng & 1023;

    const uint32_t* A32 = (const uint32_t*)Af;
    const uint32_t* W32 = (const uint32_t*)g_wf + (size_t)w * (HID * HID / 2);
    const float* bias   = (w == 0) ? bq : (w == 1) ? bk : bv;
    uint32_t* OH32      = (uint32_t*)((w == 0) ? g_qf : (w == 1) ? g_kf : g_vf);

    const uint32_t smbase = s2u(sm);

    auto gload = [&](int kc, int st) {
        uint32_t base = smbase + (uint32_t)st * GSTAGE * 4u;
        #pragma unroll
        for (int j = 0; j < 2; j++) {
            int idx = tid + j * 256;
            int row = idx >> 2, v = idx & 3;
            uint32_t so = (uint32_t)(row * 20 + v * 4) * 4u;
            cp16(base + so,               A32 + (size_t)(m0 + row) * 512 + kc * 16 + v * 4);
            cp16(base + 2560u*4u + so,    W32 + (size_t)(n0 + row) * 512 + kc * 16 + v * 4);
        }
    };

    float acc[2][8][4] = {};

    gload(0, 0); CP_COMMIT();
    gload(1, 1); CP_COMMIT();

    for (int kc = 0; kc < 32; kc++) {
        CP_WAIT1();
        __syncthreads();
        if (kc + 2 < 32) gload(kc + 2, (kc + 2) % 3);
        CP_COMMIT();

        unsigned* st = sm + (kc % 3) * GSTAGE;
        unsigned* sA = st;
        unsigned* sW = st + 2560;

        #pragma unroll
        for (int kk = 0; kk < 2; kk++) {
            unsigned a[2][4];
            #pragma unroll
            for (int mt = 0; mt < 2; mt++) {
                int base = wm * 32 + mt * 16;
                a[mt][0] = sA[(base + r)     * 20 + kk * 8 + c];
                a[mt][1] = sA[(base + r + 8) * 20 + kk * 8 + c];
                a[mt][2] = sA[(base + r)     * 20 + kk * 8 + c + 4];
                a[mt][3] = sA[(base + r + 8) * 20 + kk * 8 + c + 4];
            }
            #pragma unroll
            for (int nt = 0; nt < 8; nt++) {
                int n = wn * 64 + nt * 8 + r;
                unsigned b0 = sW[n * 20 + kk * 8 + c];
                unsigned b1 = sW[n * 20 + kk * 8 + c + 4];
                #pragma unroll
                for (int mt = 0; mt < 2; mt++)
                    mma_h(acc[mt][nt], a[mt], b0, b1);
            }
        }
    }

    #pragma unroll
    for (int mt = 0; mt < 2; mt++) {
        #pragma unroll
        for (int nt = 0; nt < 8; nt++) {
            int row = m0 + wm * 32 + mt * 16 + r;
            int col = n0 + wn * 64 + nt * 8 + 2 * c;
            float v00 = acc[mt][nt][0] + bias[col];
            float v01 = acc[mt][nt][1] + bias[col + 1];
            float v10 = acc[mt][nt][2] + bias[col];
            float v11 = acc[mt][nt][3] + bias[col + 1];
            int hh = col >> 6, d = col & 63;
            int bb0 = row >> 11, s0 = row & (SEQ - 1);
            int bb1 = (row + 8) >> 11, s1 = (row + 8) & (SEQ - 1);
            size_t o0 = ((((size_t)(bb0 * NHEAD + hh)) * SEQ + s0) * HDIM + d) / 2;
            size_t o1 = ((((size_t)(bb1 * NHEAD + hh)) * SEQ + s1) * HDIM + d) / 2;
            OH32[o0] = pack2h(__float2half_rn(v00), __float2half_rn(v01));
            OH32[o1] = pack2h(__float2half_rn(v10), __float2half_rn(v11));
        }
    }
}

// ---------------- output GEMM (3-stage, R12-proven) ----------------
__global__ __launch_bounds__(256, 2) void gemmO(
    const __half* __restrict__ Af, const float* __restrict__ bias, float* __restrict__ outF)
{
    extern __shared__ unsigned sm[];

    const int tid  = threadIdx.x;
    const int lane = tid & 31, warp = tid >> 5;
    const int wm = warp >> 1, wn = warp & 1;
    const int r = lane >> 2, c = lane & 3;
    const int m0 = blockIdx.y * 128, n0 = blockIdx.x * 128;

    const uint32_t* A32 = (const uint32_t*)Af;
    const uint32_t* W32 = (const uint32_t*)g_wf + 3 * (size_t)(HID * HID / 2);

    const uint32_t smbase = s2u(sm);

    auto gload = [&](int kc, int st) {
        uint32_t base = smbase + (uint32_t)st * GSTAGE * 4u;
        #pragma unroll
        for (int j = 0; j < 2; j++) {
            int idx = tid + j * 256;
            int row = idx >> 2, v = idx & 3;
            uint32_t so = (uint32_t)(row * 20 + v * 4) * 4u;
            cp16(base + so,            A32 + (size_t)(m0 + row) * 512 + kc * 16 + v * 4);
            cp16(base + 2560u*4u + so, W32 + (size_t)(n0 + row) * 512 + kc * 16 + v * 4);
        }
    };

    float acc[2][8][4] = {};

    gload(0, 0); CP_COMMIT();
    gload(1, 1); CP_COMMIT();

    for (int kc = 0; kc < 32; kc++) {
        CP_WAIT1();
        __syncthreads();
        if (kc + 2 < 32) gload(kc + 2, (kc + 2) % 3);
        CP_COMMIT();

        unsigned* st = sm + (kc % 3) * GSTAGE;
        unsigned* sA = st;
        unsigned* sW = st + 2560;

        #pragma unroll
        for (int kk = 0; kk < 2; kk++) {
            unsigned a[2][4];
            #pragma unroll
            for (int mt = 0; mt < 2; mt++) {
                int base = wm * 32 + mt * 16;
                a[mt][0] = sA[(base + r)     * 20 + kk * 8 + c];
                a[mt][1] = sA[(base + r + 8) * 20 + kk * 8 + c];
                a[mt][2] = sA[(base + r)     * 20 + kk * 8 + c + 4];
                a[mt][3] = sA[(base + r + 8) * 20 + kk * 8 + c + 4];
            }
            #pragma unroll
            for (int nt = 0; nt < 8; nt++) {
                int n = wn * 64 + nt * 8 + r;
                unsigned b0 = sW[n * 20 + kk * 8 + c];
                unsigned b1 = sW[n * 20 + kk * 8 + c + 4];
                #pragma unroll
                for (int mt = 0; mt < 2; mt++)
                    mma_h(acc[mt][nt], a[mt], b0, b1);
            }
        }
    }

    #pragma unroll
    for (int mt = 0; mt < 2; mt++) {
        #pragma unroll
        for (int nt = 0; nt < 8; nt++) {
            int row = m0 + wm * 32 + mt * 16 + r;
            int col = n0 + wn * 64 + nt * 8 + 2 * c;
            float b0v = bias[col], b1v = bias[col + 1];
            outF[(size_t)row * HID + col]           = acc[mt][nt][0] + b0v;
            outF[(size_t)row * HID + col + 1]       = acc[mt][nt][1] + b1v;
            outF[(size_t)(row + 8) * HID + col]     = acc[mt][nt][2] + b0v;
            outF[(size_t)(row + 8) * HID + col + 1] = acc[mt][nt][3] + b1v;
        }
    }
}

// ---------------- V transpose (unchanged) ----------------
__global__ __launch_bounds__(256) void transV()
{
    __shared__ __half t[64][66];
    const int tid = threadIdx.x;
    const int s0  = blockIdx.x * 64;
    const int bh  = blockIdx.y;

    const uint32_t* V32 = (const uint32_t*)g_vf + (size_t)bh * SEQ * 32;
    uint32_t* T32 = (uint32_t*)g_vtf + (size_t)bh * HDIM * (SEQ / 2);

    #pragma unroll
    for (int j = 0; j < 8; j++) {
        int idx = tid + j * 256;
        int row = idx >> 5, p = idx & 31;
        *(uint32_t*)&t[row][2 * p] = V32[(size_t)(s0 + row) * 32 + p];
    }
    __syncthreads();
    #pragma unroll
    for (int j = 0; j < 8; j++) {
        int idx = tid + j * 256;
        int d = idx >> 5, q = idx & 31;
        T32[(size_t)d * (SEQ / 2) + s0 / 2 + q] = pack2h(t[2 * q][d], t[2 * q + 1][d]);
    }
}

// ---------------- fused attention: cross-tile pipelined (PV lags 1 tile) ----------------
// CTA: 128 q-rows, 256 threads, 8 warps x 16 q. 32 k-tiles of 64.
// 4-slot smem ring, prefetch distance 2 (wait_group 1).
// Iteration kt: S_t -> PV_{t-1} (tensor stays fed) -> ex2_t -> pack aP_t.
__global__ __launch_bounds__(256, 2) void attn16(const float* __restrict__ mask)
{
    extern __shared__ unsigned sm[];

    const int tid  = threadIdx.x;
    const int lane = tid & 31, warp = tid >> 5;
    const int r = lane >> 2, c = lane & 3;
    const int bh = blockIdx.y;
    const int bb = bh >> 4, h = bh & 15;
    const int q0 = blockIdx.x * 128;

    const uint32_t* Qf32 = (const uint32_t*)g_qf + (size_t)bh * SEQ * 32;
    const uint32_t* Kf32 = (const uint32_t*)g_kf + (size_t)bh * SEQ * 32;
    const uint32_t* T32  = (const uint32_t*)g_vtf + (size_t)bh * HDIM * (SEQ / 2);

    const uint32_t smbase = s2u(sm);

    auto aload = [&](int kt, int st) {
        uint32_t base = smbase + (uint32_t)st * ASTAGE * 4u;
        const int k0 = kt * 64;
        #pragma unroll
        for (int j = 0; j < 2; j++) {
            int idx = tid + j * 256;             // 0..511
            int row = idx >> 3, v = idx & 7;
            uint32_t so = (uint32_t)(row * 36 + v * 4) * 4u;
            cp16(base + so,            Kf32 + (size_t)(k0 + row) * 32 + v * 4);
            cp16(base + 2304u*4u + so, T32 + (size_t)row * (SEQ / 2) + k0 / 2 + v * 4);
        }
    };

    unsigned qf[4][4];
    {
        int qr = q0 + warp * 16 + r;
        const uint32_t* rf0 = Qf32 + (size_t)qr * 32;
        const uint32_t* rf8 = Qf32 + (size_t)(qr + 8) * 32;
        #pragma unroll
        for (int kk = 0; kk < 4; kk++) {
            qf[kk][0] = rf0[kk * 8 + c];     qf[kk][1] = rf8[kk * 8 + c];
            qf[kk][2] = rf0[kk * 8 + c + 4]; qf[kk][3] = rf8[kk * 8 + c + 4];
        }
    }

    float o[8][4] = {};
    float lsum_lo = 0.0f, lsum_hi = 0.0f;
    unsigned aPp[4][4];   // P fragments of previous tile

    aload(0, 0); CP_COMMIT();
    aload(1, 1); CP_COMMIT();

    for (int kt = 0; kt < SEQ / 64; kt++) {
        const int k0 = kt * 64;

        CP_WAIT1();
        __syncthreads();
        if (kt + 2 < SEQ / 64) aload(kt + 2, (kt + 2) & 3);
        CP_COMMIT();

        unsigned* sK = sm + (kt & 3) * ASTAGE;                 // K of tile kt
        unsigned* sVp = sm + ((kt + 3) & 3) * ASTAGE + 2304;   // V of tile kt-1

        // S_t = Q K_t^T
        float s[8][4] = {};
        #pragma unroll
        for (int kk = 0; kk < 4; kk++) {
            #pragma unroll
            for (int nt = 0; nt < 8; nt++) {
                int n = nt * 8 + r;
                unsigned b0 = sK[n * 36 + kk * 8 + c];
                unsigned b1 = sK[n * 36 + kk * 8 + c + 4];
                mma_h(s[nt], qf[kk], b0, b1);
            }
        }

        // PV_{t-1}: issues into the tensor pipe while ex2_t below waits on S_t
        if (kt > 0) {
            #pragma unroll
            for (int kk = 0; kk < 4; kk++) {
                #pragma unroll
                for (int nt = 0; nt < 8; nt++) {
                    int d = nt * 8 + r;
                    unsigned b0 = sVp[d * 36 + kk * 8 + c];
                    unsigned b1 = sVp[d * 36 + kk * 8 + c + 4];
                    mma_h(o[nt], aPp[kk], b0, b1);
                }
            }
        }

        // fixed-max softmax: p = ex2(s*0.125*log2e + mask*log2e)
        #pragma unroll
        for (int nt = 0; nt < 8; nt++) {
            int col = k0 + nt * 8 + 2 * c;
            float mk0 = __ldg(mask + (size_t)bb * SEQ + col)     * LOG2E;
            float mk1 = __ldg(mask + (size_t)bb * SEQ + col + 1) * LOG2E;
            s[nt][0] = ex2(fmaf(s[nt][0], SC2, mk0));
            s[nt][1] = ex2(fmaf(s[nt][1], SC2, mk1));
            s[nt][2] = ex2(fmaf(s[nt][2], SC2, mk0));
            s[nt][3] = ex2(fmaf(s[nt][3], SC2, mk1));
            lsum_lo += s[nt][0] + s[nt][1];
            lsum_hi += s[nt][2] + s[nt][3];
        }

        // pack P_t fragments for next iteration's PV
        #pragma unroll
        for (int kk = 0; kk < 4; kk++) {
            aPp[kk][0] = pack2h(__float2half_rn(s[2*kk][0]),   __float2half_rn(s[2*kk][1]));
            aPp[kk][1] = pack2h(__float2half_rn(s[2*kk][2]),   __float2half_rn(s[2*kk][3]));
            aPp[kk][2] = pack2h(__float2half_rn(s[2*kk+1][0]), __float2half_rn(s[2*kk+1][1]));
            aPp[kk][3] = pack2h(__float2half_rn(s[2*kk+1][2]), __float2half_rn(s[2*kk+1][3]));
        }
    }

    // drain: PV for the last tile (slot 31 & 3 = 3; no loads pending)
    {
        unsigned* sVl = sm + ((SEQ / 64 - 1) & 3) * ASTAGE + 2304;
        #pragma unroll
        for (int kk = 0; kk < 4; kk++) {
            #pragma unroll
            for (int nt = 0; nt < 8; nt++) {
                int d = nt * 8 + r;
                unsigned b0 = sVl[d * 36 + kk * 8 + c];
                unsigned b1 = sVl[d * 36 + kk * 8 + c + 4];
                mma_h(o[nt], aPp[kk], b0, b1);
            }
        }
    }

    // reduce l across the quad
    #pragma unroll
    for (int d = 1; d <= 2; d <<= 1) {
        lsum_lo += __shfl_xor_sync(0xffffffffu, lsum_lo, d);
        lsum_hi += __shfl_xor_sync(0xffffffffu, lsum_hi, d);
    }
    float inv_lo = 1.0f / lsum_lo;
    float inv_hi = 1.0f / lsum_hi;

    uint32_t* Cf = (uint32_t*)g_cxf;
    size_t mrow  = (size_t)bb * SEQ + q0 + warp * 16 + r;
    size_t mrow8 = mrow + 8;
    #pragma unroll
    for (int nt = 0; nt < 8; nt++) {
        int col = h * 64 + nt * 8 + 2 * c;
        Cf[(mrow  * HID + col) / 2] =
            pack2h(__float2half_rn(o[nt][0] * inv_lo), __float2half_rn(o[nt][1] * inv_lo));
        Cf[(mrow8 * HID + col) / 2] =
            pack2h(__float2half_rn(o[nt][2] * inv_hi), __float2half_rn(o[nt][3] * inv_hi));
    }
}

// ---------------------------------------------------------------------------

extern "C" void kernel_launch(void* const* d_in, const int* in_sizes, int n_in,
                              void* d_out, int out_size)
{
    const float* hs   = (const float*)d_in[0];
    const float* mask = (const float*)d_in[1];
    const float* Wq   = (const float*)d_in[2];
    const float* bq   = (const float*)d_in[3];
    const float* Wk   = (const float*)d_in[4];
    const float* bk   = (const float*)d_in[5];
    const float* Wv   = (const float*)d_in[6];
    const float* bv   = (const float*)d_in[7];
    const float* Wo   = (const float*)d_in[8];
    const float* bo   = (const float*)d_in[9];
    float* out = (float*)d_out;

    __half *hsf, *wf, *cxf;
    cudaGetSymbolAddress((void**)&hsf, g_hsf);
    cudaGetSymbolAddress((void**)&wf,  g_wf);
    cudaGetSymbolAddress((void**)&cxf, g_cxf);

    const int gemm_smem = 3 * GSTAGE * 4;   // 61,440 B
    const int attn_smem = 4 * ASTAGE * 4;   // 73,728 B
    cudaFuncSetAttribute(gemmQKV, cudaFuncAttributeMaxDynamicSharedMemorySize, gemm_smem);
    cudaFuncSetAttribute(gemmO,   cudaFuncAttributeMaxDynamicSharedMemorySize, gemm_smem);
    cudaFuncSetAttribute(attn16,  cudaFuncAttributeMaxDynamicSharedMemorySize, attn_smem);

    dim3 blk(256);
    const int nHS = MROWS * HID / 4;
    const int nW  = HID * HID / 4;

    conv16<<<nHS / 256, blk>>>((const float4*)hs, (uint2*)hsf, nHS);
    dim3 gW(nW / 256, 4);
    conv16x4<<<gW, blk>>>((const float4*)Wq, (const float4*)Wk,
                          (const float4*)Wv, (const float4*)Wo, (uint2*)wf, nW);

    dim3 gQKV(3 * HID / 128, MROWS / 128);   // (24, 32)
    gemmQKV<<<gQKV, blk, gemm_smem>>>(hsf, bq, bk, bv);

    dim3 gT(SEQ / 64, BH);                   // (32, 32)
    transV<<<gT, blk>>>();

    dim3 gA(SEQ / 128, BH);                  // (16, 32)
    attn16<<<gA, blk, attn_smem>>>(mask);

    dim3 gO(HID / 128, MROWS / 128);         // (8, 32)
    gemmO<<<gO, blk, gemm_smem>>>(cxf, bo, out);
}

// round 16
// speedup vs baseline: 1.0442x; 1.0442x over previous
#include <cuda_runtime.h>
#include <cuda_fp16.h>
#include <cstdint>

#define BATCH 2
#define SEQ   2048
#define HID   1024
#define NHEAD 16
#define HDIM  64
#define MROWS (BATCH*SEQ)   // 4096
#define BH    (BATCH*NHEAD) // 32

// ---------------- device scratch (allocation-free rule) ----------------
__device__ __half g_hsf[MROWS*HID];                     // hidden states plain fp16
__device__ __half g_wf[4*HID*HID];                      // Wq,Wk,Wv,Wo plain fp16
__device__ __half g_qf[BH*SEQ*HDIM];                    // Q plain [bh][s][d]
__device__ __half g_kf[BH*SEQ*HDIM];                    // K plain [bh][s][d]
__device__ __half g_vtf[BH*HDIM*SEQ];                   // V^T plain [bh][d][s]
__device__ __half g_cxf[MROWS*HID];                     // ctx plain [m][n]

// ---------------- helpers ----------------
__device__ __forceinline__ unsigned pack2h(__half a, __half b) {
    __half2 t(a, b);
    return *reinterpret_cast<unsigned*>(&t);
}
__device__ __forceinline__ void mma_h(float* c, const unsigned* a,
                                      unsigned b0, unsigned b1) {
    asm volatile(
        "mma.sync.aligned.m16n8k16.row.col.f32.f16.f16.f32 "
        "{%0,%1,%2,%3},{%4,%5,%6,%7},{%8,%9},{%0,%1,%2,%3};\n"
        : "+f"(c[0]), "+f"(c[1]), "+f"(c[2]), "+f"(c[3])
        : "r"(a[0]), "r"(a[1]), "r"(a[2]), "r"(a[3]), "r"(b0), "r"(b1));
}
__device__ __forceinline__ uint32_t s2u(const void* p) {
    uint32_t a;
    asm("{ .reg .u64 t; cvta.to.shared.u64 t, %1; cvt.u32.u64 %0, t; }" : "=r"(a) : "l"(p));
    return a;
}
__device__ __forceinline__ void cp16(uint32_t saddr, const void* gaddr) {
    asm volatile("cp.async.cg.shared.global [%0], [%1], 16;" :: "r"(saddr), "l"(gaddr));
}
#define CP_COMMIT() asm volatile("cp.async.commit_group;" ::: "memory")
#define CP_WAIT1()  asm volatile("cp.async.wait_group 1;" ::: "memory")

#define GSTAGE 5120    // gemm stage: A(128x20)+W(128x20) u32 = 20 KB
#define ASTAGE 4608    // attn stage: K(64x36)+Vt(64x36) u32 = 18.4 KB

// ---------------- fp32 -> fp16 convert: weights (y=0..3) + hs quarters (y=4..7) ----------------
__global__ void conv_all(const float4* __restrict__ hs,
                         const float4* __restrict__ w0, const float4* __restrict__ w1,
                         const float4* __restrict__ w2, const float4* __restrict__ w3,
                         uint2* __restrict__ hsf, uint2* __restrict__ wf)
{
    const int nW = HID * HID / 4;            // 262,144 float4 per matrix
    int i = blockIdx.x * 256 + threadIdx.x;  // 0..nW-1
    int y = blockIdx.y;

    const float4* src;
    uint2* dst;
    if (y < 4) {
        src = (y == 0) ? w0 : (y == 1) ? w1 : (y == 2) ? w2 : w3;
        dst = wf + (size_t)y * nW;
    } else {
        src = hs + (size_t)(y - 4) * nW;
        dst = hsf + (size_t)(y - 4) * nW;
    }
    float4 v = src[i];
    uint2 o;
    o.x = pack2h(__float2half_rn(v.x), __float2half_rn(v.y));
    o.y = pack2h(__float2half_rn(v.z), __float2half_rn(v.w));
    dst[i] = o;
}

// ---------------- fused QKV GEMM (3-stage; V written transposed) ----------------
__global__ __launch_bounds__(256, 2) void gemmQKV(
    const __half* __restrict__ Af,
    const float* __restrict__ bq, const float* __restrict__ bk, const float* __restrict__ bv)
{
    extern __shared__ unsigned sm[];

    const int tid  = threadIdx.x;
    const int lane = tid & 31, warp = tid >> 5;
    const int wm = warp >> 1, wn = warp & 1;
    const int r = lane >> 2, c = lane & 3;
    const int m0 = blockIdx.y * 128;
    const int ng = blockIdx.x * 128;
    const int w  = ng >> 10;                  // 0=Q 1=K 2=V
    const int n0 = ng & 1023;

    const uint32_t* A32 = (const uint32_t*)Af;
    const uint32_t* W32 = (const uint32_t*)g_wf + (size_t)w * (HID * HID / 2);
    const float* bias   = (w == 0) ? bq : (w == 1) ? bk : bv;

    const uint32_t smbase = s2u(sm);

    auto gload = [&](int kc, int st) {
        uint32_t base = smbase + (uint32_t)st * GSTAGE * 4u;
        #pragma unroll
        for (int j = 0; j < 2; j++) {
            int idx = tid + j * 256;
            int row = idx >> 2, v = idx & 3;
            uint32_t so = (uint32_t)(row * 20 + v * 4) * 4u;
            cp16(base + so,               A32 + (size_t)(m0 + row) * 512 + kc * 16 + v * 4);
            cp16(base + 2560u*4u + so,    W32 + (size_t)(n0 + row) * 512 + kc * 16 + v * 4);
        }
    };

    float acc[2][8][4] = {};

    gload(0, 0); CP_COMMIT();
    gload(1, 1); CP_COMMIT();

    for (int kc = 0; kc < 32; kc++) {
        CP_WAIT1();
        __syncthreads();
        if (kc + 2 < 32) gload(kc + 2, (kc + 2) % 3);
        CP_COMMIT();

        unsigned* st = sm + (kc % 3) * GSTAGE;
        unsigned* sA = st;
        unsigned* sW = st + 2560;

        #pragma unroll
        for (int kk = 0; kk < 2; kk++) {
            unsigned a[2][4];
            #pragma unroll
            for (int mt = 0; mt < 2; mt++) {
                int base = wm * 32 + mt * 16;
                a[mt][0] = sA[(base + r)     * 20 + kk * 8 + c];
                a[mt][1] = sA[(base + r + 8) * 20 + kk * 8 + c];
                a[mt][2] = sA[(base + r)     * 20 + kk * 8 + c + 4];
                a[mt][3] = sA[(base + r + 8) * 20 + kk * 8 + c + 4];
            }
            #pragma unroll
            for (int nt = 0; nt < 8; nt++) {
                int n = wn * 64 + nt * 8 + r;
                unsigned b0 = sW[n * 20 + kk * 8 + c];
                unsigned b1 = sW[n * 20 + kk * 8 + c + 4];
                #pragma unroll
                for (int mt = 0; mt < 2; mt++)
                    mma_h(acc[mt][nt], a[mt], b0, b1);
            }
        }
    }

    if (w < 2) {
        // Q / K: head-split [bh][s][d], packed u32 stores
        uint32_t* OH32 = (uint32_t*)((w == 0) ? g_qf : g_kf);
        #pragma unroll
        for (int mt = 0; mt < 2; mt++) {
            #pragma unroll
            for (int nt = 0; nt < 8; nt++) {
                int row = m0 + wm * 32 + mt * 16 + r;
                int col = n0 + wn * 64 + nt * 8 + 2 * c;
                float v00 = acc[mt][nt][0] + bias[col];
                float v01 = acc[mt][nt][1] + bias[col + 1];
                float v10 = acc[mt][nt][2] + bias[col];
                float v11 = acc[mt][nt][3] + bias[col + 1];
                int hh = col >> 6, d = col & 63;
                int bb = row >> 11, s0 = row & (SEQ - 1);
                size_t o0 = ((((size_t)(bb * NHEAD + hh)) * SEQ + s0) * HDIM + d) / 2;
                size_t o1 = o0 + 8 * HDIM / 2;   // row+8, same tile/batch
                OH32[o0] = pack2h(__float2half_rn(v00), __float2half_rn(v01));
                OH32[o1] = pack2h(__float2half_rn(v10), __float2half_rn(v11));
            }
        }
    } else {
        // V: write directly transposed into [bh][d][s] (fused transV)
        #pragma unroll
        for (int mt = 0; mt < 2; mt++) {
            #pragma unroll
            for (int nt = 0; nt < 8; nt++) {
                int row = m0 + wm * 32 + mt * 16 + r;   // s index (within batch after mask)
                int col = n0 + wn * 64 + nt * 8 + 2 * c;
                float v00 = acc[mt][nt][0] + bias[col];
                float v01 = acc[mt][nt][1] + bias[col + 1];
                float v10 = acc[mt][nt][2] + bias[col];
                float v11 = acc[mt][nt][3] + bias[col + 1];
                int hh = col >> 6, d = col & 63;
                int bb = row >> 11, s0 = row & (SEQ - 1);
                size_t base = ((size_t)(bb * NHEAD + hh) * HDIM + d) * SEQ;
                g_vtf[base + s0]            = __float2half_rn(v00);
                g_vtf[base + SEQ + s0]      = __float2half_rn(v01);   // d+1
                g_vtf[base + s0 + 8]        = __float2half_rn(v10);   // row+8
                g_vtf[base + SEQ + s0 + 8]  = __float2half_rn(v11);
            }
        }
    }
}

// ---------------- output GEMM (3-stage, R12-proven) ----------------
__global__ __launch_bounds__(256, 2) void gemmO(
    const __half* __restrict__ Af, const float* __restrict__ bias, float* __restrict__ outF)
{
    extern __shared__ unsigned sm[];

    const int tid  = threadIdx.x;
    const int lane = tid & 31, warp = tid >> 5;
    const int wm = warp >> 1, wn = warp & 1;
    const int r = lane >> 2, c = lane & 3;
    const int m0 = blockIdx.y * 128, n0 = blockIdx.x * 128;

    const uint32_t* A32 = (const uint32_t*)Af;
    const uint32_t* W32 = (const uint32_t*)g_wf + 3 * (size_t)(HID * HID / 2);

    const uint32_t smbase = s2u(sm);

    auto gload = [&](int kc, int st) {
        uint32_t base = smbase + (uint32_t)st * GSTAGE * 4u;
        #pragma unroll
        for (int j = 0; j < 2; j++) {
            int idx = tid + j * 256;
            int row = idx >> 2, v = idx & 3;
            uint32_t so = (uint32_t)(row * 20 + v * 4) * 4u;
            cp16(base + so,            A32 + (size_t)(m0 + row) * 512 + kc * 16 + v * 4);
            cp16(base + 2560u*4u + so, W32 + (size_t)(n0 + row) * 512 + kc * 16 + v * 4);
        }
    };

    float acc[2][8][4] = {};

    gload(0, 0); CP_COMMIT();
    gload(1, 1); CP_COMMIT();

    for (int kc = 0; kc < 32; kc++) {
        CP_WAIT1();
        __syncthreads();
        if (kc + 2 < 32) gload(kc + 2, (kc + 2) % 3);
        CP_COMMIT();

        unsigned* st = sm + (kc % 3) * GSTAGE;
        unsigned* sA = st;
        unsigned* sW = st + 2560;

        #pragma unroll
        for (int kk = 0; kk < 2; kk++) {
            unsigned a[2][4];
            #pragma unroll
            for (int mt = 0; mt < 2; mt++) {
                int base = wm * 32 + mt * 16;
                a[mt][0] = sA[(base + r)     * 20 + kk * 8 + c];
                a[mt][1] = sA[(base + r + 8) * 20 + kk * 8 + c];
                a[mt][2] = sA[(base + r)     * 20 + kk * 8 + c + 4];
                a[mt][3] = sA[(base + r + 8) * 20 + kk * 8 + c + 4];
            }
            #pragma unroll
            for (int nt = 0; nt < 8; nt++) {
                int n = wn * 64 + nt * 8 + r;
                unsigned b0 = sW[n * 20 + kk * 8 + c];
                unsigned b1 = sW[n * 20 + kk * 8 + c + 4];
                #pragma unroll
                for (int mt = 0; mt < 2; mt++)
                    mma_h(acc[mt][nt], a[mt], b0, b1);
            }
        }
    }

    #pragma unroll
    for (int mt = 0; mt < 2; mt++) {
        #pragma unroll
        for (int nt = 0; nt < 8; nt++) {
            int row = m0 + wm * 32 + mt * 16 + r;
            int col = n0 + wn * 64 + nt * 8 + 2 * c;
            float b0v = bias[col], b1v = bias[col + 1];
            outF[(size_t)row * HID + col]           = acc[mt][nt][0] + b0v;
            outF[(size_t)row * HID + col + 1]       = acc[mt][nt][1] + b1v;
            outF[(size_t)(row + 8) * HID + col]     = acc[mt][nt][2] + b0v;
            outF[(size_t)(row + 8) * HID + col + 1] = acc[mt][nt][3] + b1v;
        }
    }
}

// ---------------- fused attention (R12-proven: 3-stage, __expf) ----------------
// CTA: 128 q-rows, 256 threads, 8 warps x 16 q. 32 k-tiles of 64.
__global__ __launch_bounds__(256, 2) void attn16(const float* __restrict__ mask)
{
    extern __shared__ unsigned sm[];

    const int tid  = threadIdx.x;
    const int lane = tid & 31, warp = tid >> 5;
    const int r = lane >> 2, c = lane & 3;
    const int bh = blockIdx.y;
    const int bb = bh >> 4, h = bh & 15;
    const int q0 = blockIdx.x * 128;

    const uint32_t* Qf32 = (const uint32_t*)g_qf + (size_t)bh * SEQ * 32;
    const uint32_t* Kf32 = (const uint32_t*)g_kf + (size_t)bh * SEQ * 32;
    const uint32_t* T32  = (const uint32_t*)g_vtf + (size_t)bh * HDIM * (SEQ / 2);

    const uint32_t smbase = s2u(sm);

    auto aload = [&](int kt, int st) {
        uint32_t base = smbase + (uint32_t)st * ASTAGE * 4u;
        const int k0 = kt * 64;
        #pragma unroll
        for (int j = 0; j < 2; j++) {
            int idx = tid + j * 256;             // 0..511
            int row = idx >> 3, v = idx & 7;
            uint32_t so = (uint32_t)(row * 36 + v * 4) * 4u;
            cp16(base + so,            Kf32 + (size_t)(k0 + row) * 32 + v * 4);
            cp16(base + 2304u*4u + so, T32 + (size_t)row * (SEQ / 2) + k0 / 2 + v * 4);
        }
    };

    unsigned qf[4][4];
    {
        int qr = q0 + warp * 16 + r;
        const uint32_t* rf0 = Qf32 + (size_t)qr * 32;
        const uint32_t* rf8 = Qf32 + (size_t)(qr + 8) * 32;
        #pragma unroll
        for (int kk = 0; kk < 4; kk++) {
            qf[kk][0] = rf0[kk * 8 + c];     qf[kk][1] = rf8[kk * 8 + c];
            qf[kk][2] = rf0[kk * 8 + c + 4]; qf[kk][3] = rf8[kk * 8 + c + 4];
        }
    }

    float o[8][4] = {};
    float lsum_lo = 0.0f, lsum_hi = 0.0f;

    aload(0, 0); CP_COMMIT();
    aload(1, 1); CP_COMMIT();

    for (int kt = 0; kt < SEQ / 64; kt++) {
        const int k0 = kt * 64;

        CP_WAIT1();
        __syncthreads();
        if (kt + 2 < SEQ / 64) aload(kt + 2, (kt + 2) % 3);
        CP_COMMIT();

        unsigned* st = sm + (kt % 3) * ASTAGE;
        unsigned* sK = st;
        unsigned* sV = st + 2304;

        // S = Q K^T (1-term fp16)
        float s[8][4] = {};
        #pragma unroll
        for (int kk = 0; kk < 4; kk++) {
            #pragma unroll
            for (int nt = 0; nt < 8; nt++) {
                int n = nt * 8 + r;
                unsigned b0 = sK[n * 36 + kk * 8 + c];
                unsigned b1 = sK[n * 36 + kk * 8 + c + 4];
                mma_h(s[nt], qf[kk], b0, b1);
            }
        }

        // fixed-max softmax: p = exp(s/8 + mask); accumulate l in registers
        #pragma unroll
        for (int nt = 0; nt < 8; nt++) {
            int col = k0 + nt * 8 + 2 * c;
            float mk0 = __ldg(mask + (size_t)bb * SEQ + col);
            float mk1 = __ldg(mask + (size_t)bb * SEQ + col + 1);
            s[nt][0] = __expf(fmaf(s[nt][0], 0.125f, mk0));
            s[nt][1] = __expf(fmaf(s[nt][1], 0.125f, mk1));
            s[nt][2] = __expf(fmaf(s[nt][2], 0.125f, mk0));
            s[nt][3] = __expf(fmaf(s[nt][3], 0.125f, mk1));
            lsum_lo += s[nt][0] + s[nt][1];
            lsum_hi += s[nt][2] + s[nt][3];
        }

        // P: C-frag layout == A-frag layout; pack plain fp16 in registers
        unsigned aP[4][4];
        #pragma unroll
        for (int kk = 0; kk < 4; kk++) {
            aP[kk][0] = pack2h(__float2half_rn(s[2*kk][0]),   __float2half_rn(s[2*kk][1]));
            aP[kk][1] = pack2h(__float2half_rn(s[2*kk][2]),   __float2half_rn(s[2*kk][3]));
            aP[kk][2] = pack2h(__float2half_rn(s[2*kk+1][0]), __float2half_rn(s[2*kk+1][1]));
            aP[kk][3] = pack2h(__float2half_rn(s[2*kk+1][2]), __float2half_rn(s[2*kk+1][3]));
        }

        // O += P V (1-term), B from smem V^T
        #pragma unroll
        for (int kk = 0; kk < 4; kk++) {
            #pragma unroll
            for (int nt = 0; nt < 8; nt++) {
                int d = nt * 8 + r;
                unsigned b0 = sV[d * 36 + kk * 8 + c];
                unsigned b1 = sV[d * 36 + kk * 8 + c + 4];
                mma_h(o[nt], aP[kk], b0, b1);
            }
        }
    }

    // reduce l across the quad
    #pragma unroll
    for (int d = 1; d <= 2; d <<= 1) {
        lsum_lo += __shfl_xor_sync(0xffffffffu, lsum_lo, d);
        lsum_hi += __shfl_xor_sync(0xffffffffu, lsum_hi, d);
    }
    float inv_lo = 1.0f / lsum_lo;
    float inv_hi = 1.0f / lsum_hi;

    uint32_t* Cf = (uint32_t*)g_cxf;
    size_t mrow  = (size_t)bb * SEQ + q0 + warp * 16 + r;
    size_t mrow8 = mrow + 8;
    #pragma unroll
    for (int nt = 0; nt < 8; nt++) {
        int col = h * 64 + nt * 8 + 2 * c;
        Cf[(mrow  * HID + col) / 2] =
            pack2h(__float2half_rn(o[nt][0] * inv_lo), __float2half_rn(o[nt][1] * inv_lo));
        Cf[(mrow8 * HID + col) / 2] =
            pack2h(__float2half_rn(o[nt][2] * inv_hi), __float2half_rn(o[nt][3] * inv_hi));
    }
}

// ---------------------------------------------------------------------------

extern "C" void kernel_launch(void* const* d_in, const int* in_sizes, int n_in,
                              void* d_out, int out_size)
{
    const float* hs   = (const float*)d_in[0];
    const float* mask = (const float*)d_in[1];
    const float* Wq   = (const float*)d_in[2];
    const float* bq   = (const float*)d_in[3];
    const float* Wk   = (const float*)d_in[4];
    const float* bk   = (const float*)d_in[5];
    const float* Wv   = (const float*)d_in[6];
    const float* bv   = (const float*)d_in[7];
    const float* Wo   = (const float*)d_in[8];
    const float* bo   = (const float*)d_in[9];
    float* out = (float*)d_out;

    __half *hsf, *wf, *cxf;
    cudaGetSymbolAddress((void**)&hsf, g_hsf);
    cudaGetSymbolAddress((void**)&wf,  g_wf);
    cudaGetSymbolAddress((void**)&cxf, g_cxf);

    const int gemm_smem = 3 * GSTAGE * 4;   // 61,440 B
    const int attn_smem = 3 * ASTAGE * 4;   // 55,296 B
    cudaFuncSetAttribute(gemmQKV, cudaFuncAttributeMaxDynamicSharedMemorySize, gemm_smem);
    cudaFuncSetAttribute(gemmO,   cudaFuncAttributeMaxDynamicSharedMemorySize, gemm_smem);
    cudaFuncSetAttribute(attn16,  cudaFuncAttributeMaxDynamicSharedMemorySize, attn_smem);

    dim3 blk(256);
    const int nW = HID * HID / 4;   // 262,144 float4 per matrix / per hs quarter

    // single conversion launch: 4 weight matrices + 4 hs quarters
    dim3 gC(nW / 256, 8);
    conv_all<<<gC, blk>>>((const float4*)hs,
                          (const float4*)Wq, (const float4*)Wk,
                          (const float4*)Wv, (const float4*)Wo,
                          (uint2*)hsf, (uint2*)wf);

    dim3 gQKV(3 * HID / 128, MROWS / 128);   // (24, 32) — V written transposed
    gemmQKV<<<gQKV, blk, gemm_smem>>>(hsf, bq, bk, bv);

    dim3 gA(SEQ / 128, BH);                  // (16, 32)
    attn16<<<gA, blk, attn_smem>>>(mask);

    dim3 gO(HID / 128, MROWS / 128);         // (8, 32)
    gemmO<<<gO, blk, gemm_smem>>>(cxf, bo, out);
}

// round 17
// speedup vs baseline: 1.1335x; 1.0856x over previous
#include <cuda_runtime.h>
#include <cuda_fp16.h>
#include <cstdint>

#define BATCH 2
#define SEQ   2048
#define HID   1024
#define NHEAD 16
#define HDIM  64
#define MROWS (BATCH*SEQ)   // 4096
#define BH    (BATCH*NHEAD) // 32

// ---------------- device scratch (allocation-free rule) ----------------
__device__ __half g_hsf[MROWS*HID];                     // hidden states plain fp16
__device__ __half g_wf[4*HID*HID];                      // Wq,Wk,Wv,Wo plain fp16
__device__ __half g_qf[BH*SEQ*HDIM];                    // Q plain [bh][s][d]
__device__ __half g_kf[BH*SEQ*HDIM];                    // K plain [bh][s][d]
__device__ __half g_vtf[BH*HDIM*SEQ];                   // V^T plain [bh][d][s]
__device__ __half g_cxf[MROWS*HID];                     // ctx plain [m][n]

// ---------------- helpers ----------------
__device__ __forceinline__ unsigned pack2h(__half a, __half b) {
    __half2 t(a, b);
    return *reinterpret_cast<unsigned*>(&t);
}
__device__ __forceinline__ void mma_h(float* c, const unsigned* a,
                                      unsigned b0, unsigned b1) {
    asm volatile(
        "mma.sync.aligned.m16n8k16.row.col.f32.f16.f16.f32 "
        "{%0,%1,%2,%3},{%4,%5,%6,%7},{%8,%9},{%0,%1,%2,%3};\n"
        : "+f"(c[0]), "+f"(c[1]), "+f"(c[2]), "+f"(c[3])
        : "r"(a[0]), "r"(a[1]), "r"(a[2]), "r"(a[3]), "r"(b0), "r"(b1));
}
__device__ __forceinline__ void ldsm4(unsigned &r0, unsigned &r1,
                                      unsigned &r2, unsigned &r3, uint32_t addr) {
    asm volatile("ldmatrix.sync.aligned.m8n8.x4.shared.b16 {%0,%1,%2,%3}, [%4];"
                 : "=r"(r0), "=r"(r1), "=r"(r2), "=r"(r3) : "r"(addr));
}
__device__ __forceinline__ uint32_t s2u(const void* p) {
    uint32_t a;
    asm("{ .reg .u64 t; cvta.to.shared.u64 t, %1; cvt.u32.u64 %0, t; }" : "=r"(a) : "l"(p));
    return a;
}
__device__ __forceinline__ void cp16(uint32_t saddr, const void* gaddr) {
    asm volatile("cp.async.cg.shared.global [%0], [%1], 16;" :: "r"(saddr), "l"(gaddr));
}
#define CP_COMMIT() asm volatile("cp.async.commit_group;" ::: "memory")
#define CP_WAIT1()  asm volatile("cp.async.wait_group 1;" ::: "memory")

#define GSTAGE 5120    // gemm stage: A(128x20)+W(128x20) u32 = 20 KB
#define ASTAGE 4608    // attn stage: K(64x36)+Vt(64x36) u32 = 18.4 KB

// ---------------- fp32 -> fp16 convert: weights (y=0..3) + hs quarters (y=4..7) ----------------
__global__ void conv_all(const float4* __restrict__ hs,
                         const float4* __restrict__ w0, const float4* __restrict__ w1,
                         const float4* __restrict__ w2, const float4* __restrict__ w3,
                         uint2* __restrict__ hsf, uint2* __restrict__ wf)
{
    const int nW = HID * HID / 4;
    int i = blockIdx.x * 256 + threadIdx.x;
    int y = blockIdx.y;

    const float4* src;
    uint2* dst;
    if (y < 4) {
        src = (y == 0) ? w0 : (y == 1) ? w1 : (y == 2) ? w2 : w3;
        dst = wf + (size_t)y * nW;
    } else {
        src = hs + (size_t)(y - 4) * nW;
        dst = hsf + (size_t)(y - 4) * nW;
    }
    float4 v = src[i];
    uint2 o;
    o.x = pack2h(__float2half_rn(v.x), __float2half_rn(v.y));
    o.y = pack2h(__float2half_rn(v.z), __float2half_rn(v.w));
    dst[i] = o;
}

// ---------------- fused QKV GEMM (3-stage; ldmatrix; V written transposed) ----------------
__global__ __launch_bounds__(256, 2) void gemmQKV(
    const __half* __restrict__ Af,
    const float* __restrict__ bq, const float* __restrict__ bk, const float* __restrict__ bv)
{
    extern __shared__ unsigned sm[];

    const int tid  = threadIdx.x;
    const int lane = tid & 31, warp = tid >> 5;
    const int wm = warp >> 1, wn = warp & 1;
    const int r = lane >> 2, c = lane & 3;
    const int m0 = blockIdx.y * 128;
    const int ng = blockIdx.x * 128;
    const int w  = ng >> 10;                  // 0=Q 1=K 2=V
    const int n0 = ng & 1023;

    const uint32_t* A32 = (const uint32_t*)Af;
    const uint32_t* W32 = (const uint32_t*)g_wf + (size_t)w * (HID * HID / 2);
    const float* bias   = (w == 0) ? bq : (w == 1) ? bk : bv;

    const uint32_t smbase = s2u(sm);
    const int l7 = lane & 7;
    // lane offsets for ldmatrix, pitch 80 B
    const uint32_t lofA = (uint32_t)((l7 + ((lane & 8)  ? 8 : 0)) * 80 + ((lane & 16) ? 16 : 0));
    const uint32_t lofB = (uint32_t)((l7 + ((lane & 16) ? 8 : 0)) * 80 + ((lane & 8)  ? 16 : 0));

    auto gload = [&](int kc, int st) {
        uint32_t base = smbase + (uint32_t)st * GSTAGE * 4u;
        #pragma unroll
        for (int j = 0; j < 2; j++) {
            int idx = tid + j * 256;
            int row = idx >> 2, v = idx & 3;
            uint32_t so = (uint32_t)(row * 20 + v * 4) * 4u;
            cp16(base + so,               A32 + (size_t)(m0 + row) * 512 + kc * 16 + v * 4);
            cp16(base + 2560u*4u + so,    W32 + (size_t)(n0 + row) * 512 + kc * 16 + v * 4);
        }
    };

    float acc[2][8][4] = {};

    gload(0, 0); CP_COMMIT();
    gload(1, 1); CP_COMMIT();

    for (int kc = 0; kc < 32; kc++) {
        CP_WAIT1();
        __syncthreads();
        if (kc + 2 < 32) gload(kc + 2, (kc + 2) % 3);
        CP_COMMIT();

        uint32_t sAb = smbase + (uint32_t)(kc % 3) * GSTAGE * 4u;
        uint32_t sWb = sAb + 2560u * 4u;

        #pragma unroll
        for (int kk = 0; kk < 2; kk++) {
            unsigned a[2][4];
            #pragma unroll
            for (int mt = 0; mt < 2; mt++)
                ldsm4(a[mt][0], a[mt][1], a[mt][2], a[mt][3],
                      sAb + (uint32_t)((wm * 32 + mt * 16) * 80 + kk * 32) + lofA);
            #pragma unroll
            for (int j = 0; j < 4; j++) {
                unsigned b0, b1, b2, b3;
                ldsm4(b0, b1, b2, b3,
                      sWb + (uint32_t)((wn * 64 + 16 * j) * 80 + kk * 32) + lofB);
                #pragma unroll
                for (int mt = 0; mt < 2; mt++) {
                    mma_h(acc[mt][2*j],     a[mt], b0, b1);
                    mma_h(acc[mt][2*j + 1], a[mt], b2, b3);
                }
            }
        }
    }

    if (w < 2) {
        uint32_t* OH32 = (uint32_t*)((w == 0) ? g_qf : g_kf);
        #pragma unroll
        for (int mt = 0; mt < 2; mt++) {
            #pragma unroll
            for (int nt = 0; nt < 8; nt++) {
                int row = m0 + wm * 32 + mt * 16 + r;
                int col = n0 + wn * 64 + nt * 8 + 2 * c;
                float v00 = acc[mt][nt][0] + bias[col];
                float v01 = acc[mt][nt][1] + bias[col + 1];
                float v10 = acc[mt][nt][2] + bias[col];
                float v11 = acc[mt][nt][3] + bias[col + 1];
                int hh = col >> 6, d = col & 63;
                int bb = row >> 11, s0 = row & (SEQ - 1);
                size_t o0 = ((((size_t)(bb * NHEAD + hh)) * SEQ + s0) * HDIM + d) / 2;
                size_t o1 = o0 + 8 * HDIM / 2;
                OH32[o0] = pack2h(__float2half_rn(v00), __float2half_rn(v01));
                OH32[o1] = pack2h(__float2half_rn(v10), __float2half_rn(v11));
            }
        }
    } else {
        #pragma unroll
        for (int mt = 0; mt < 2; mt++) {
            #pragma unroll
            for (int nt = 0; nt < 8; nt++) {
                int row = m0 + wm * 32 + mt * 16 + r;
                int col = n0 + wn * 64 + nt * 8 + 2 * c;
                float v00 = acc[mt][nt][0] + bias[col];
                float v01 = acc[mt][nt][1] + bias[col + 1];
                float v10 = acc[mt][nt][2] + bias[col];
                float v11 = acc[mt][nt][3] + bias[col + 1];
                int hh = col >> 6, d = col & 63;
                int bb = row >> 11, s0 = row & (SEQ - 1);
                size_t base = ((size_t)(bb * NHEAD + hh) * HDIM + d) * SEQ;
                g_vtf[base + s0]            = __float2half_rn(v00);
                g_vtf[base + SEQ + s0]      = __float2half_rn(v01);
                g_vtf[base + s0 + 8]        = __float2half_rn(v10);
                g_vtf[base + SEQ + s0 + 8]  = __float2half_rn(v11);
            }
        }
    }
}

// ---------------- output GEMM (3-stage; ldmatrix) ----------------
__global__ __launch_bounds__(256, 2) void gemmO(
    const __half* __restrict__ Af, const float* __restrict__ bias, float* __restrict__ outF)
{
    extern __shared__ unsigned sm[];

    const int tid  = threadIdx.x;
    const int lane = tid & 31, warp = tid >> 5;
    const int wm = warp >> 1, wn = warp & 1;
    const int r = lane >> 2, c = lane & 3;
    const int m0 = blockIdx.y * 128, n0 = blockIdx.x * 128;

    const uint32_t* A32 = (const uint32_t*)Af;
    const uint32_t* W32 = (const uint32_t*)g_wf + 3 * (size_t)(HID * HID / 2);

    const uint32_t smbase = s2u(sm);
    const int l7 = lane & 7;
    const uint32_t lofA = (uint32_t)((l7 + ((lane & 8)  ? 8 : 0)) * 80 + ((lane & 16) ? 16 : 0));
    const uint32_t lofB = (uint32_t)((l7 + ((lane & 16) ? 8 : 0)) * 80 + ((lane & 8)  ? 16 : 0));

    auto gload = [&](int kc, int st) {
        uint32_t base = smbase + (uint32_t)st * GSTAGE * 4u;
        #pragma unroll
        for (int j = 0; j < 2; j++) {
            int idx = tid + j * 256;
            int row = idx >> 2, v = idx & 3;
            uint32_t so = (uint32_t)(row * 20 + v * 4) * 4u;
            cp16(base + so,            A32 + (size_t)(m0 + row) * 512 + kc * 16 + v * 4);
            cp16(base + 2560u*4u + so, W32 + (size_t)(n0 + row) * 512 + kc * 16 + v * 4);
        }
    };

    float acc[2][8][4] = {};

    gload(0, 0); CP_COMMIT();
    gload(1, 1); CP_COMMIT();

    for (int kc = 0; kc < 32; kc++) {
        CP_WAIT1();
        __syncthreads();
        if (kc + 2 < 32) gload(kc + 2, (kc + 2) % 3);
        CP_COMMIT();

        uint32_t sAb = smbase + (uint32_t)(kc % 3) * GSTAGE * 4u;
        uint32_t sWb = sAb + 2560u * 4u;

        #pragma unroll
        for (int kk = 0; kk < 2; kk++) {
            unsigned a[2][4];
            #pragma unroll
            for (int mt = 0; mt < 2; mt++)
                ldsm4(a[mt][0], a[mt][1], a[mt][2], a[mt][3],
                      sAb + (uint32_t)((wm * 32 + mt * 16) * 80 + kk * 32) + lofA);
            #pragma unroll
            for (int j = 0; j < 4; j++) {
                unsigned b0, b1, b2, b3;
                ldsm4(b0, b1, b2, b3,
                      sWb + (uint32_t)((wn * 64 + 16 * j) * 80 + kk * 32) + lofB);
                #pragma unroll
                for (int mt = 0; mt < 2; mt++) {
                    mma_h(acc[mt][2*j],     a[mt], b0, b1);
                    mma_h(acc[mt][2*j + 1], a[mt], b2, b3);
                }
            }
        }
    }

    #pragma unroll
    for (int mt = 0; mt < 2; mt++) {
        #pragma unroll
        for (int nt = 0; nt < 8; nt++) {
            int row = m0 + wm * 32 + mt * 16 + r;
            int col = n0 + wn * 64 + nt * 8 + 2 * c;
            float b0v = bias[col], b1v = bias[col + 1];
            outF[(size_t)row * HID + col]           = acc[mt][nt][0] + b0v;
            outF[(size_t)row * HID + col + 1]       = acc[mt][nt][1] + b1v;
            outF[(size_t)(row + 8) * HID + col]     = acc[mt][nt][2] + b0v;
            outF[(size_t)(row + 8) * HID + col + 1] = acc[mt][nt][3] + b1v;
        }
    }
}

// ---------------- fused attention (3-stage; ldmatrix B operands) ----------------
// CTA: 128 q-rows, 256 threads, 8 warps x 16 q. 32 k-tiles of 64.
__global__ __launch_bounds__(256, 2) void attn16(const float* __restrict__ mask)
{
    extern __shared__ unsigned sm[];

    const int tid  = threadIdx.x;
    const int lane = tid & 31, warp = tid >> 5;
    const int r = lane >> 2, c = lane & 3;
    const int bh = blockIdx.y;
    const int bb = bh >> 4, h = bh & 15;
    const int q0 = blockIdx.x * 128;

    const uint32_t* Qf32 = (const uint32_t*)g_qf + (size_t)bh * SEQ * 32;
    const uint32_t* Kf32 = (const uint32_t*)g_kf + (size_t)bh * SEQ * 32;
    const uint32_t* T32  = (const uint32_t*)g_vtf + (size_t)bh * HDIM * (SEQ / 2);

    const uint32_t smbase = s2u(sm);
    const int l7 = lane & 7;
    // B lane offset, pitch 144 B
    const uint32_t lofB = (uint32_t)((l7 + ((lane & 16) ? 8 : 0)) * 144 + ((lane & 8) ? 16 : 0));

    auto aload = [&](int kt, int st) {
        uint32_t base = smbase + (uint32_t)st * ASTAGE * 4u;
        const int k0 = kt * 64;
        #pragma unroll
        for (int j = 0; j < 2; j++) {
            int idx = tid + j * 256;
            int row = idx >> 3, v = idx & 7;
            uint32_t so = (uint32_t)(row * 36 + v * 4) * 4u;
            cp16(base + so,            Kf32 + (size_t)(k0 + row) * 32 + v * 4);
            cp16(base + 2304u*4u + so, T32 + (size_t)row * (SEQ / 2) + k0 / 2 + v * 4);
        }
    };

    unsigned qf[4][4];
    {
        int qr = q0 + warp * 16 + r;
        const uint32_t* rf0 = Qf32 + (size_t)qr * 32;
        const uint32_t* rf8 = Qf32 + (size_t)(qr + 8) * 32;
        #pragma unroll
        for (int kk = 0; kk < 4; kk++) {
            qf[kk][0] = rf0[kk * 8 + c];     qf[kk][1] = rf8[kk * 8 + c];
            qf[kk][2] = rf0[kk * 8 + c + 4]; qf[kk][3] = rf8[kk * 8 + c + 4];
        }
    }

    float o[8][4] = {};
    float lsum_lo = 0.0f, lsum_hi = 0.0f;

    aload(0, 0); CP_COMMIT();
    aload(1, 1); CP_COMMIT();

    for (int kt = 0; kt < SEQ / 64; kt++) {
        const int k0 = kt * 64;

        CP_WAIT1();
        __syncthreads();
        if (kt + 2 < SEQ / 64) aload(kt + 2, (kt + 2) % 3);
        CP_COMMIT();

        uint32_t sKb = smbase + (uint32_t)(kt % 3) * ASTAGE * 4u;
        uint32_t sVb = sKb + 2304u * 4u;

        // S = Q K^T (1-term fp16), B via ldmatrix.x4 (2 nt per load)
        float s[8][4] = {};
        #pragma unroll
        for (int kk = 0; kk < 4; kk++) {
            #pragma unroll
            for (int j = 0; j < 4; j++) {
                unsigned b0, b1, b2, b3;
                ldsm4(b0, b1, b2, b3, sKb + (uint32_t)(j * 2304 + kk * 32) + lofB);
                mma_h(s[2*j],     qf[kk], b0, b1);
                mma_h(s[2*j + 1], qf[kk], b2, b3);
            }
        }

        // fixed-max softmax
        #pragma unroll
        for (int nt = 0; nt < 8; nt++) {
            int col = k0 + nt * 8 + 2 * c;
            float mk0 = __ldg(mask + (size_t)bb * SEQ + col);
            float mk1 = __ldg(mask + (size_t)bb * SEQ + col + 1);
            s[nt][0] = __expf(fmaf(s[nt][0], 0.125f, mk0));
            s[nt][1] = __expf(fmaf(s[nt][1], 0.125f, mk1));
            s[nt][2] = __expf(fmaf(s[nt][2], 0.125f, mk0));
            s[nt][3] = __expf(fmaf(s[nt][3], 0.125f, mk1));
            lsum_lo += s[nt][0] + s[nt][1];
            lsum_hi += s[nt][2] + s[nt][3];
        }

        // P fragments
        unsigned aP[4][4];
        #pragma unroll
        for (int kk = 0; kk < 4; kk++) {
            aP[kk][0] = pack2h(__float2half_rn(s[2*kk][0]),   __float2half_rn(s[2*kk][1]));
            aP[kk][1] = pack2h(__float2half_rn(s[2*kk][2]),   __float2half_rn(s[2*kk][3]));
            aP[kk][2] = pack2h(__float2half_rn(s[2*kk+1][0]), __float2half_rn(s[2*kk+1][1]));
            aP[kk][3] = pack2h(__float2half_rn(s[2*kk+1][2]), __float2half_rn(s[2*kk+1][3]));
        }

        // O += P V (1-term), V^T via ldmatrix.x4
        #pragma unroll
        for (int kk = 0; kk < 4; kk++) {
            #pragma unroll
            for (int j = 0; j < 4; j++) {
                unsigned b0, b1, b2, b3;
                ldsm4(b0, b1, b2, b3, sVb + (uint32_t)(j * 2304 + kk * 32) + lofB);
                mma_h(o[2*j],     aP[kk], b0, b1);
                mma_h(o[2*j + 1], aP[kk], b2, b3);
            }
        }
    }

    // reduce l across the quad
    #pragma unroll
    for (int d = 1; d <= 2; d <<= 1) {
        lsum_lo += __shfl_xor_sync(0xffffffffu, lsum_lo, d);
        lsum_hi += __shfl_xor_sync(0xffffffffu, lsum_hi, d);
    }
    float inv_lo = 1.0f / lsum_lo;
    float inv_hi = 1.0f / lsum_hi;

    uint32_t* Cf = (uint32_t*)g_cxf;
    size_t mrow  = (size_t)bb * SEQ + q0 + warp * 16 + r;
    size_t mrow8 = mrow + 8;
    #pragma unroll
    for (int nt = 0; nt < 8; nt++) {
        int col = h * 64 + nt * 8 + 2 * c;
        Cf[(mrow  * HID + col) / 2] =
            pack2h(__float2half_rn(o[nt][0] * inv_lo), __float2half_rn(o[nt][1] * inv_lo));
        Cf[(mrow8 * HID + col) / 2] =
            pack2h(__float2half_rn(o[nt][2] * inv_hi), __float2half_rn(o[nt][3] * inv_hi));
    }
}

// ---------------------------------------------------------------------------

extern "C" void kernel_launch(void* const* d_in, const int* in_sizes, int n_in,
                              void* d_out, int out_size)
{
    const float* hs   = (const float*)d_in[0];
    const float* mask = (const float*)d_in[1];
    const float* Wq   = (const float*)d_in[2];
    const float* bq   = (const float*)d_in[3];
    const float* Wk   = (const float*)d_in[4];
    const float* bk   = (const float*)d_in[5];
    const float* Wv   = (const float*)d_in[6];
    const float* bv   = (const float*)d_in[7];
    const float* Wo   = (const float*)d_in[8];
    const float* bo   = (const float*)d_in[9];
    float* out = (float*)d_out;

    __half *hsf, *wf, *cxf;
    cudaGetSymbolAddress((void**)&hsf, g_hsf);
    cudaGetSymbolAddress((void**)&wf,  g_wf);
    cudaGetSymbolAddress((void**)&cxf, g_cxf);

    const int gemm_smem = 3 * GSTAGE * 4;   // 61,440 B
    const int attn_smem = 3 * ASTAGE * 4;   // 55,296 B
    cudaFuncSetAttribute(gemmQKV, cudaFuncAttributeMaxDynamicSharedMemorySize, gemm_smem);
    cudaFuncSetAttribute(gemmO,   cudaFuncAttributeMaxDynamicSharedMemorySize, gemm_smem);
    cudaFuncSetAttribute(attn16,  cudaFuncAttributeMaxDynamicSharedMemorySize, attn_smem);

    dim3 blk(256);
    const int nW = HID * HID / 4;

    dim3 gC(nW / 256, 8);
    conv_all<<<gC, blk>>>((const float4*)hs,
                          (const float4*)Wq, (const float4*)Wk,
                          (const float4*)Wv, (const float4*)Wo,
                          (uint2*)hsf, (uint2*)wf);

    dim3 gQKV(3 * HID / 128, MROWS / 128);   // (24, 32)
    gemmQKV<<<gQKV, blk, gemm_smem>>>(hsf, bq, bk, bv);

    dim3 gA(SEQ / 128, BH);                  // (16, 32)
    attn16<<<gA, blk, attn_smem>>>(mask);

    dim3 gO(HID / 128, MROWS / 128);         // (8, 32)
    gemmO<<<gO, blk, gemm_smem>>>(cxf, bo, out);
}